// round 2
// baseline (speedup 1.0000x reference)
#include <cuda_runtime.h>
#include <math.h>

// Problem constants
#define B_     8
#define T_     512
#define C_     512
#define L_     4
#define NH_    8
#define DH_    64
#define S_     1024          // 2*T interleaved sequence
#define MROWS  8192          // B_ * S_
#define FF_    2048          // 4*C
#define SD_    48
#define AD_    12

// ---------------------------------------------------------------------------
// Scratch: one big static device buffer, carved by offsets (no allocation).
// Layout (floats):
//   H    [MROWS*C_]
//   tmp  [MROWS*C_]
//   q    [MROWS*C_]
//   k    [MROWS*C_]
//   v    [MROWS*C_]
//   att  [MROWS*C_]
//   ff   [MROWS*FF_]
// ---------------------------------------------------------------------------
#define OFF_H    0
#define OFF_TMP  (MROWS * C_)
#define OFF_Q    (2 * MROWS * C_)
#define OFF_K    (3 * MROWS * C_)
#define OFF_V    (4 * MROWS * C_)
#define OFF_ATT  (5 * MROWS * C_)
#define OFF_FF   (6 * MROWS * C_)
#define SCRATCH_FLOATS (6 * MROWS * C_ + MROWS * FF_)

__device__ float g_scratch[SCRATCH_FLOATS];

// ---------------------------------------------------------------------------
// Embedding + interleave + LayerNorm (one block per token row)
// ---------------------------------------------------------------------------
__global__ __launch_bounds__(256) void embed_kernel(
    const float* __restrict__ states, const float* __restrict__ actions,
    const float* __restrict__ We_s, const float* __restrict__ be_s,
    const float* __restrict__ We_a, const float* __restrict__ be_a,
    const float* __restrict__ pe,
    const float* __restrict__ g, const float* __restrict__ bt,
    float* __restrict__ H)
{
    __shared__ float xs[SD_];
    __shared__ float rs[256], rq[256];

    int row = blockIdx.x;            // 0..8191
    int b   = row >> 10;
    int s   = row & 1023;
    int t   = s >> 1;
    int act = s & 1;
    int tid = threadIdx.x;

    int K            = act ? AD_ : SD_;
    const float* x   = act ? (actions + ((size_t)b * T_ + t) * AD_)
                           : (states  + ((size_t)b * T_ + t) * SD_);
    const float* W   = act ? We_a : We_s;
    const float* bia = act ? be_a : be_s;

    if (tid < K) xs[tid] = x[tid];
    __syncthreads();

    float v[2];
    float sum = 0.f, sumsq = 0.f;
#pragma unroll
    for (int e = 0; e < 2; e++) {
        int c = tid + e * 256;
        float a = bia[c] + pe[t * C_ + c];
        const float* wr = W + (size_t)c * K;
        for (int k = 0; k < K; k++) a += xs[k] * wr[k];
        v[e] = a;
        sum += a; sumsq += a * a;
    }
    rs[tid] = sum; rq[tid] = sumsq;
    __syncthreads();
    for (int off = 128; off > 0; off >>= 1) {
        if (tid < off) { rs[tid] += rs[tid + off]; rq[tid] += rq[tid + off]; }
        __syncthreads();
    }
    float mean = rs[0] * (1.f / C_);
    float var  = rq[0] * (1.f / C_) - mean * mean;
    float rstd = rsqrtf(var + 1e-5f);

#pragma unroll
    for (int e = 0; e < 2; e++) {
        int c = tid + e * 256;
        H[(size_t)row * C_ + c] = (v[e] - mean) * rstd * g[c] + bt[c];
    }
}

// ---------------------------------------------------------------------------
// LayerNorm (one block per row)
// ---------------------------------------------------------------------------
__global__ __launch_bounds__(256) void ln_kernel(
    const float* __restrict__ in, float* __restrict__ out,
    const float* __restrict__ g, const float* __restrict__ bt)
{
    __shared__ float rs[256], rq[256];
    int row = blockIdx.x;
    int tid = threadIdx.x;
    const float* x = in + (size_t)row * C_;

    float v0 = x[tid], v1 = x[tid + 256];
    rs[tid] = v0 + v1; rq[tid] = v0 * v0 + v1 * v1;
    __syncthreads();
    for (int off = 128; off > 0; off >>= 1) {
        if (tid < off) { rs[tid] += rs[tid + off]; rq[tid] += rq[tid + off]; }
        __syncthreads();
    }
    float mean = rs[0] * (1.f / C_);
    float var  = rq[0] * (1.f / C_) - mean * mean;
    float rstd = rsqrtf(var + 1e-5f);

    float* o = out + (size_t)row * C_;
    o[tid]       = (v0 - mean) * rstd * g[tid]       + bt[tid];
    o[tid + 256] = (v1 - mean) * rstd * g[tid + 256] + bt[tid + 256];
}

// ---------------------------------------------------------------------------
// Generic SGEMM:  out[M,Nn] = A[M,K] @ W[Nn,K]^T + bias (+resid) (gelu?)
// headLayout=1 scatters output into [B*NH, S, DH] (for Q/K/V).
// BM=BN=128, BK=16, 256 threads, 8x8 microtile.
// ---------------------------------------------------------------------------
__device__ __forceinline__ void gemm_body(
    const float* __restrict__ A, const float* __restrict__ W,
    const float* __restrict__ bias, const float* __restrict__ resid,
    float* __restrict__ out, int M, int Nn, int K, int gelu, int headLayout,
    int bx, int by)
{
    __shared__ float As[16][128];
    __shared__ float Bs[16][128];

    int tid = threadIdx.x;
    int tx  = tid & 15;       // 0..15 -> n direction
    int ty  = tid >> 4;       // 0..15 -> m direction
    int m0  = by * 128;
    int n0  = bx * 128;

    float acc[8][8];
#pragma unroll
    for (int i = 0; i < 8; i++)
#pragma unroll
        for (int j = 0; j < 8; j++) acc[i][j] = 0.f;

    for (int k0 = 0; k0 < K; k0 += 16) {
        // cooperative load, transpose into k-major smem
#pragma unroll
        for (int l = tid; l < 512; l += 256) {
            int r  = l >> 2;
            int c4 = (l & 3) * 4;
            float4 va = *(const float4*)(A + (size_t)(m0 + r) * K + k0 + c4);
            As[c4 + 0][r] = va.x; As[c4 + 1][r] = va.y;
            As[c4 + 2][r] = va.z; As[c4 + 3][r] = va.w;
            float4 vb = *(const float4*)(W + (size_t)(n0 + r) * K + k0 + c4);
            Bs[c4 + 0][r] = vb.x; Bs[c4 + 1][r] = vb.y;
            Bs[c4 + 2][r] = vb.z; Bs[c4 + 3][r] = vb.w;
        }
        __syncthreads();

#pragma unroll
        for (int kk = 0; kk < 16; kk++) {
            float a[8], bb[8];
            *(float4*)(a)      = *(const float4*)&As[kk][ty * 8];
            *(float4*)(a + 4)  = *(const float4*)&As[kk][ty * 8 + 4];
            *(float4*)(bb)     = *(const float4*)&Bs[kk][tx * 8];
            *(float4*)(bb + 4) = *(const float4*)&Bs[kk][tx * 8 + 4];
#pragma unroll
            for (int i = 0; i < 8; i++)
#pragma unroll
                for (int j = 0; j < 8; j++) acc[i][j] += a[i] * bb[j];
        }
        __syncthreads();
    }

    // epilogue
#pragma unroll
    for (int i = 0; i < 8; i++) {
        int m = m0 + ty * 8 + i;
#pragma unroll
        for (int j = 0; j < 8; j++) {
            int n = n0 + tx * 8 + j;
            float v = acc[i][j] + bias[n];
            if (resid) v += resid[(size_t)m * Nn + n];
            if (gelu)  v = 0.5f * v * (1.f + erff(v * 0.70710678118654752f));
            if (headLayout) {
                int bb2 = m >> 10, s = m & 1023, hd = n >> 6, d = n & 63;
                out[(((size_t)(bb2 * NH_ + hd) * S_) + s) * DH_ + d] = v;
            } else {
                out[(size_t)m * Nn + n] = v;
            }
        }
    }
}

__global__ __launch_bounds__(256) void gemm_kernel(
    const float* __restrict__ A, const float* __restrict__ W,
    const float* __restrict__ bias, const float* __restrict__ resid,
    float* __restrict__ out, int M, int Nn, int K, int gelu, int headLayout)
{
    gemm_body(A, W, bias, resid, out, M, Nn, K, gelu, headLayout,
              blockIdx.x, blockIdx.y);
}

// Fused Q/K/V projection: grid.x = 12; blocks 0-3 -> Q, 4-7 -> K, 8-11 -> V.
__global__ __launch_bounds__(256) void qkv_kernel(
    const float* __restrict__ A,
    const float* __restrict__ Wq, const float* __restrict__ bq,
    const float* __restrict__ Wk, const float* __restrict__ bk,
    const float* __restrict__ Wv, const float* __restrict__ bv,
    float* __restrict__ qo, float* __restrict__ ko, float* __restrict__ vo)
{
    int which = blockIdx.x >> 2;     // 0,1,2
    int bx    = blockIdx.x & 3;
    const float* W   = (which == 0) ? Wq : (which == 1) ? Wk : Wv;
    const float* bia = (which == 0) ? bq : (which == 1) ? bk : bv;
    float* out       = (which == 0) ? qo : (which == 1) ? ko : vo;
    gemm_body(A, W, bia, nullptr, out, MROWS, C_, C_, 0, 1, bx, blockIdx.y);
}

// ---------------------------------------------------------------------------
// Fused causal flash-attention (fp32).  Tq=Tk=32, 128 threads.
// q/k/v: [B*NH, S, DH].  Output written to [M, C] (heads re-merged).
// ---------------------------------------------------------------------------
__global__ __launch_bounds__(128) void attn_kernel(
    const float* __restrict__ Q, const float* __restrict__ K,
    const float* __restrict__ V, float* __restrict__ att)
{
    __shared__ float Qs[32][68];
    __shared__ float Ks[32][68];
    __shared__ float Vs[32][68];
    __shared__ float Ps[32][36];

    int tid  = threadIdx.x;
    int head = blockIdx.y;                 // b*NH + n
    int q0   = blockIdx.x * 32;
    size_t base = (size_t)head * S_ * DH_;

    // load Q tile (scaled by 1/sqrt(D))
    {
        int r  = tid >> 2;
        int c0 = (tid & 3) * 16;
        const float* src = Q + base + (size_t)(q0 + r) * DH_ + c0;
#pragma unroll
        for (int c = 0; c < 16; c++) Qs[r][c0 + c] = src[c] * 0.125f;
    }

    int i  = tid >> 2;   // query row 0..31 (8 rows per warp)
    int tx = tid & 3;

    float acc[16];
#pragma unroll
    for (int c = 0; c < 16; c++) acc[c] = 0.f;
    float m_i = -1e30f, l_i = 0.f;

    for (int kt = 0; kt <= (int)blockIdx.x; kt++) {
        int k0 = kt * 32;
        __syncthreads();   // protect K/V/Ps from previous iteration (and Qs 1st iter)
        {
            int r  = tid >> 2;
            int c0 = (tid & 3) * 16;
            const float* ks = K + base + (size_t)(k0 + r) * DH_ + c0;
            const float* vs = V + base + (size_t)(k0 + r) * DH_ + c0;
#pragma unroll
            for (int c = 0; c < 16; c++) { Ks[r][c0 + c] = ks[c]; Vs[r][c0 + c] = vs[c]; }
        }
        __syncthreads();

        // scores: this thread owns j = jj*4 + tx  (conflict-free K reads)
        float sc[8];
#pragma unroll
        for (int jj = 0; jj < 8; jj++) sc[jj] = 0.f;
        const float4* qrow = (const float4*)Qs[i];
#pragma unroll
        for (int d4 = 0; d4 < 16; d4++) {
            float4 qv = qrow[d4];
#pragma unroll
            for (int jj = 0; jj < 8; jj++) {
                int j = jj * 4 + tx;
                float4 kv = ((const float4*)Ks[j])[d4];
                sc[jj] += qv.x * kv.x + qv.y * kv.y + qv.z * kv.z + qv.w * kv.w;
            }
        }
        // causal mask
#pragma unroll
        for (int jj = 0; jj < 8; jj++) {
            int j = jj * 4 + tx;
            if (k0 + j > q0 + i) sc[jj] = -1e30f;
        }
        // row max across 8 local + 4 lanes
        float mx = sc[0];
#pragma unroll
        for (int jj = 1; jj < 8; jj++) mx = fmaxf(mx, sc[jj]);
        mx = fmaxf(mx, __shfl_xor_sync(0xffffffffu, mx, 1));
        mx = fmaxf(mx, __shfl_xor_sync(0xffffffffu, mx, 2));
        float m_new = fmaxf(m_i, mx);

        float sum = 0.f;
#pragma unroll
        for (int jj = 0; jj < 8; jj++) {
            int j = jj * 4 + tx;
            float p = __expf(sc[jj] - m_new);
            Ps[i][j] = p;
            sum += p;
        }
        sum += __shfl_xor_sync(0xffffffffu, sum, 1);
        sum += __shfl_xor_sync(0xffffffffu, sum, 2);

        float scale = __expf(m_i - m_new);
        l_i = l_i * scale + sum;
        m_i = m_new;
#pragma unroll
        for (int c = 0; c < 16; c++) acc[c] *= scale;
        __syncwarp();   // Ps produced/consumed within the same warp

        // PV accumulate into this thread's 16 output columns
        int c0 = tx * 16;
#pragma unroll 4
        for (int j = 0; j < 32; j++) {
            float p = Ps[i][j];
            const float4* vr = (const float4*)&Vs[j][c0];
            float4 v0 = vr[0], v1 = vr[1], v2 = vr[2], v3 = vr[3];
            acc[0]  += p * v0.x; acc[1]  += p * v0.y; acc[2]  += p * v0.z; acc[3]  += p * v0.w;
            acc[4]  += p * v1.x; acc[5]  += p * v1.y; acc[6]  += p * v1.z; acc[7]  += p * v1.w;
            acc[8]  += p * v2.x; acc[9]  += p * v2.y; acc[10] += p * v2.z; acc[11] += p * v2.w;
            acc[12] += p * v3.x; acc[13] += p * v3.y; acc[14] += p * v3.z; acc[15] += p * v3.w;
        }
    }

    float inv = 1.f / l_i;
    int b = head >> 3, n = head & 7;
    int row = (b << 10) + q0 + i;
    float* dst = att + (size_t)row * C_ + (n << 6) + tx * 16;
#pragma unroll
    for (int c = 0; c < 16; c++) dst[c] = acc[c] * inv;
}

// ---------------------------------------------------------------------------
// Output heads: state_preds from odd rows (action tokens), action_preds from
// even rows. out = [state_preds (B*T*48), action_preds (B*T*12)].
// ---------------------------------------------------------------------------
__global__ __launch_bounds__(64) void heads_kernel(
    const float* __restrict__ H,
    const float* __restrict__ Wps, const float* __restrict__ bps,
    const float* __restrict__ Wpa, const float* __restrict__ bpa,
    float* __restrict__ out)
{
    __shared__ float rows[2 * C_];
    int bt  = blockIdx.x;                  // b*T + t
    int b   = bt >> 9;
    int t   = bt & 511;
    int tid = threadIdx.x;

    size_t base = ((size_t)(b << 10) + (t << 1)) * C_;   // even row, odd row adjacent
    for (int j = tid; j < 2 * C_; j += 64) rows[j] = H[base + j];
    __syncthreads();

    if (tid < SD_) {
        const float* w = Wps + (size_t)tid * C_;
        float a = bps[tid];
        for (int k = 0; k < C_; k++) a += rows[C_ + k] * w[k];   // odd row
        out[(size_t)bt * SD_ + tid] = a;
    }
    if (tid < AD_) {
        const float* w = Wpa + (size_t)tid * C_;
        float a = bpa[tid];
        for (int k = 0; k < C_; k++) a += rows[k] * w[k];        // even row
        out[(size_t)(B_ * T_ * SD_) + (size_t)bt * AD_ + tid] = a;
    }
}

// ---------------------------------------------------------------------------
// Launch
// ---------------------------------------------------------------------------
extern "C" void kernel_launch(void* const* d_in, const int* in_sizes, int n_in,
                              void* d_out, int out_size)
{
    const float* states  = (const float*)d_in[0];
    const float* actions = (const float*)d_in[1];
    const float* We_s    = (const float*)d_in[2];
    const float* be_s    = (const float*)d_in[3];
    const float* We_a    = (const float*)d_in[4];
    const float* be_a    = (const float*)d_in[5];
    const float* pe      = (const float*)d_in[6];
    const float* g_emb   = (const float*)d_in[7];
    const float* b_emb   = (const float*)d_in[8];
    const float* Wq      = (const float*)d_in[9];
    const float* bq      = (const float*)d_in[10];
    const float* Wk      = (const float*)d_in[11];
    const float* bk      = (const float*)d_in[12];
    const float* Wv      = (const float*)d_in[13];
    const float* bv      = (const float*)d_in[14];
    const float* Wo      = (const float*)d_in[15];
    const float* bo      = (const float*)d_in[16];
    const float* W1      = (const float*)d_in[17];
    const float* b1      = (const float*)d_in[18];
    const float* W2      = (const float*)d_in[19];
    const float* b2      = (const float*)d_in[20];
    const float* bt1     = (const float*)d_in[22];
    const float* g1      = (const float*)d_in[21];
    const float* g2      = (const float*)d_in[23];
    const float* bt2     = (const float*)d_in[24];
    const float* Wps     = (const float*)d_in[25];
    const float* bps     = (const float*)d_in[26];
    const float* Wpa     = (const float*)d_in[27];
    const float* bpa     = (const float*)d_in[28];

    float* scratch = nullptr;
    cudaGetSymbolAddress((void**)&scratch, g_scratch);
    float* H    = scratch + OFF_H;
    float* tmp  = scratch + OFF_TMP;
    float* qb   = scratch + OFF_Q;
    float* kb   = scratch + OFF_K;
    float* vb   = scratch + OFF_V;
    float* attb = scratch + OFF_ATT;
    float* ffb  = scratch + OFF_FF;

    embed_kernel<<<MROWS, 256>>>(states, actions, We_s, be_s, We_a, be_a,
                                 pe, g_emb, b_emb, H);

    dim3 gC(C_ / 128, MROWS / 128);     // 4 x 64
    dim3 gF(FF_ / 128, MROWS / 128);    // 16 x 64
    dim3 gQKV(3 * C_ / 128, MROWS / 128);

    for (int i = 0; i < L_; i++) {
        const float* Wq_i = Wq + (size_t)i * C_ * C_;
        const float* Wk_i = Wk + (size_t)i * C_ * C_;
        const float* Wv_i = Wv + (size_t)i * C_ * C_;
        const float* Wo_i = Wo + (size_t)i * C_ * C_;
        const float* W1_i = W1 + (size_t)i * FF_ * C_;
        const float* W2_i = W2 + (size_t)i * C_ * FF_;

        qkv_kernel<<<gQKV, 256>>>(H,
                                  Wq_i, bq + i * C_,
                                  Wk_i, bk + i * C_,
                                  Wv_i, bv + i * C_,
                                  qb, kb, vb);

        attn_kernel<<<dim3(S_ / 32, B_ * NH_), 128>>>(qb, kb, vb, attb);

        gemm_kernel<<<gC, 256>>>(attb, Wo_i, bo + i * C_, H, tmp, MROWS, C_, C_, 0, 0);
        ln_kernel<<<MROWS, 256>>>(tmp, H, g1 + i * C_, bt1 + i * C_);

        gemm_kernel<<<gF, 256>>>(H, W1_i, b1 + i * FF_, nullptr, ffb, MROWS, FF_, C_, 1, 0);
        gemm_kernel<<<gC, 256>>>(ffb, W2_i, b2 + i * C_, H, tmp, MROWS, C_, FF_, 0, 0);
        ln_kernel<<<MROWS, 256>>>(tmp, H, g2 + i * C_, bt2 + i * C_);
    }

    heads_kernel<<<B_ * T_, 64>>>(H, Wps, bps, Wpa, bpa, (float*)d_out);
}